// round 15
// baseline (speedup 1.0000x reference)
#include <cuda_runtime.h>
#include <stdint.h>

#define NB 64
#define NC 768
#define NN 576
#define NG 3
#define GS 192
#define NT 1024
#define NWP 32          // warps per CTA

__device__ float g_heatP[2 * NB * NWP * NN]; // [chunk][warp][576] per-warp partials
__device__ float g_tots [2 * NB * NC];       // [chunk][c] per-channel totals
__device__ float g_gsum [2 * NB * NG * NC];  // [chunk][3*NC]
__device__ float g_partial[NB];
__device__ int   g_pair[NB];                 // self-resetting
__device__ int   g_counter;                  // self-resetting

// ---------------------------------------------------------------------------
// K1: PURE STREAM. One CTA per (img,b). Heat partials in regs, totals via
// warp shuffle, then one coalesced dump of per-warp partials. No tree, no
// serial sections, no cross-warp traffic.
// ---------------------------------------------------------------------------
__global__ __launch_bounds__(NT, 1)
void heat_kernel(const float* __restrict__ in0, const float* __restrict__ in1) {
    const int ib   = blockIdx.x;               // img*NB + b
    const int b    = ib & (NB - 1);
    const float* src = ((ib >= NB) ? in1 : in0) + (size_t)b * NC * NN;

    const int tid  = threadIdx.x;
    const int w    = tid >> 5;                 // 0..31
    const int lane = tid & 31;

    float2 acc[9];
#pragma unroll
    for (int j = 0; j < 9; ++j) acc[j] = make_float2(0.f, 0.f);

    float* tdst = g_tots + (size_t)ib * NC;
#pragma unroll 2
    for (int k = 0; k < NC / NWP; ++k) {       // 24 channels per warp
        const int c = w + NWP * k;
        const float2* row = (const float2*)(src + (size_t)c * NN);
        float2 v[9];
#pragma unroll
        for (int j = 0; j < 9; ++j) v[j] = row[lane + 32 * j];
        float t = 0.f;
#pragma unroll
        for (int j = 0; j < 9; ++j) {
            acc[j].x += v[j].x;
            acc[j].y += v[j].y;
            t += v[j].x + v[j].y;
        }
#pragma unroll
        for (int o = 16; o; o >>= 1) t += __shfl_down_sync(0xffffffffu, t, o);
        if (lane == 0) tdst[c] = t;
    }

    // dump per-warp heat partials: [chunk][w][n], n = 2*(lane+32j)(+1)
    float2* hp = (float2*)(g_heatP + ((size_t)ib * NWP + w) * NN);
#pragma unroll
    for (int j = 0; j < 9; ++j) hp[lane + 32 * j] = acc[j];
}

__device__ __forceinline__ float block_reduce(float v, float* red) {
    const int lane = threadIdx.x & 31, w = threadIdx.x >> 5;
#pragma unroll
    for (int o = 16; o; o >>= 1) v += __shfl_down_sync(0xffffffffu, v, o);
    if (lane == 0) red[w] = v;
    __syncthreads();
    if (threadIdx.x < 32) {
        v = red[threadIdx.x];
#pragma unroll
        for (int o = 16; o; o >>= 1) v += __shfl_down_sync(0xffffffffu, v, o);
        if (threadIdx.x == 0) red[0] = v;
    }
    __syncthreads();
    float r = red[0];
    __syncthreads();
    return r;
}

// ---------------------------------------------------------------------------
// K2: combine partials (fixed order) -> rank -> masked group sums (reverse,
// streaming loads; tails L2-hot from K1) -> inline pairing epilogue.
// ---------------------------------------------------------------------------
__global__ __launch_bounds__(NT, 1)
void gsum_kernel(const float* __restrict__ in0, const float* __restrict__ in1,
                 float* __restrict__ out) {
    __shared__ float         heatC[NN];
    __shared__ unsigned char slab[NN];
    __shared__ float         red[NWP];
    __shared__ int           flg;

    const int ib   = blockIdx.x;
    const int b    = ib & (NB - 1);
    const float* src = ((ib >= NB) ? in1 : in0) + (size_t)b * NC * NN;

    const int tid  = threadIdx.x;
    const int w    = tid >> 5;
    const int lane = tid & 31;

    // ---- Combine 32 per-warp partials in fixed order (deterministic)
    if (tid < NN) {
        const float* hp = g_heatP + (size_t)ib * NWP * NN + tid;
        float h = 0.f;
#pragma unroll
        for (int s = 0; s < NWP; ++s) h += hp[s * NN];
        heatC[tid] = h;
    }
    __syncthreads();

    // ---- Rank + tercile label: warp w owns n in [18w, 18w+18)
    {
        float kr[18];
#pragma unroll
        for (int j = 0; j < 18; ++j) kr[j] = heatC[lane + 32 * j];
#pragma unroll
        for (int i = 0; i < 18; ++i) {
            int n = 18 * w + i;
            float hn = heatC[n];
            unsigned cnt = 0;
#pragma unroll
            for (int j = 0; j < 18; ++j) {
                int m = lane + 32 * j;
                cnt += (kr[j] > hn) || (kr[j] == hn && m < n);
            }
            unsigned rk = __reduce_add_sync(0xffffffffu, cnt);
            if (lane == 0) slab[n] = (unsigned char)(rk / GS);
        }
    }
    __syncthreads();

    // ---- Per-lane label bitmasks (positions 2*(lane+32j), +1)
    unsigned bm0 = 0, bm1 = 0;
#pragma unroll
    for (int j = 0; j < 9; ++j) {
        int n = 2 * (lane + 32 * j);
        unsigned char l0 = slab[n], l1 = slab[n + 1];
        bm0 |= ((l0 == 0) ? 1u : 0u) << (2 * j);
        bm0 |= ((l1 == 0) ? 1u : 0u) << (2 * j + 1);
        bm1 |= ((l0 == 1) ? 1u : 0u) << (2 * j);
        bm1 |= ((l1 == 1) ? 1u : 0u) << (2 * j + 1);
    }

    // ---- Phase 2: reverse channel order (freshest-in-L2 first), streaming
    const float* tsrc = g_tots + (size_t)ib * NC;
    float* dst = g_gsum + (size_t)ib * NG * NC;
    for (int k = 0; k < NC / NWP; ++k) {
        const int c = (NC - 1) - (w + NWP * k);
        const float2* row = (const float2*)(src + (size_t)c * NN);
        float s0 = 0.f, s1 = 0.f;
#pragma unroll
        for (int j = 0; j < 9; ++j) {
            float2 v = __ldcs(&row[lane + 32 * j]);
            if ((bm0 >> (2 * j)) & 1u)     s0 += v.x;
            if ((bm0 >> (2 * j + 1)) & 1u) s0 += v.y;
            if ((bm1 >> (2 * j)) & 1u)     s1 += v.x;
            if ((bm1 >> (2 * j + 1)) & 1u) s1 += v.y;
        }
#pragma unroll
        for (int o = 16; o; o >>= 1) {
            s0 += __shfl_down_sync(0xffffffffu, s0, o);
            s1 += __shfl_down_sync(0xffffffffu, s1, o);
        }
        if (lane == 0) {
            dst[c]          = s0;
            dst[NC + c]     = s1;
            dst[2 * NC + c] = tsrc[c] - s0 - s1;   // 1/192 cancels in L2 norm
        }
    }
    __syncthreads();

    // ---- Pairing: second CTA of this b computes normalize + SSD
    if (tid == 0) {
        __threadfence();
        int prev = atomicAdd(&g_pair[b], 1);
        if (prev == 1) { g_pair[b] = 0; flg = 1; }   // self-reset for replay
        else           { flg = 0; }
    }
    __syncthreads();
    if (!flg) return;
    __threadfence();

    const float* v1 = g_gsum + (size_t)b * NG * NC;
    const float* v2 = g_gsum + (size_t)(NB + b) * NG * NC;

    float ss1 = 0.f, ss2 = 0.f;
    for (int i = tid; i < NG * NC; i += NT) {
        float a = v1[i], c = v2[i];
        ss1 = fmaf(a, a, ss1);
        ss2 = fmaf(c, c, ss2);
    }
    ss1 = block_reduce(ss1, red);
    ss2 = block_reduce(ss2, red);
    float i1 = 1.f / fmaxf(sqrtf(ss1), 1e-12f);
    float i2 = 1.f / fmaxf(sqrtf(ss2), 1e-12f);

    float acc2 = 0.f;
    for (int i = tid; i < NG * NC; i += NT) {
        float d = v1[i] * i1 - v2[i] * i2;
        acc2 = fmaf(d, d, acc2);
    }
    acc2 = block_reduce(acc2, red);

    if (tid == 0) {
        g_partial[b] = acc2;
        __threadfence();
        int prev = atomicAdd(&g_counter, 1);
        if (prev == NB - 1) { g_counter = 0; flg = 1; }
        else                { flg = 0; }
    }
    __syncthreads();

    if (flg && tid < 32) {
        float v = g_partial[tid] + g_partial[tid + 32];
#pragma unroll
        for (int o = 16; o; o >>= 1) v += __shfl_down_sync(0xffffffffu, v, o);
        if (tid == 0) out[0] = v * (1.f / (float)(NB * NG * NC));
    }
}

extern "C" void kernel_launch(void* const* d_in, const int* in_sizes, int n_in,
                              void* d_out, int out_size) {
    const float* in0 = (const float*)d_in[0];
    const float* in1 = (const float*)d_in[1];
    float* out = (float*)d_out;
    (void)in_sizes; (void)n_in; (void)out_size;

    heat_kernel<<<2 * NB, NT>>>(in0, in1);
    gsum_kernel<<<2 * NB, NT>>>(in0, in1, out);
}